// round 1
// baseline (speedup 1.0000x reference)
#include <cuda_runtime.h>
#include <cstdint>

#define NTOK  50257
#define NIN   300
#define NHID  64
#define TT    18
#define BATCH 4096

typedef unsigned long long ull;

// Precomputed input transform: EW[token][0:256] = E@W_f, EW[token][256:512] = E@W_b
__device__ float g_EW[(size_t)NTOK * 512];

// ---------- packed f32x2 helpers (sm_103a dual-rate FFMA2 path) ----------
__device__ __forceinline__ ull pk2(float a, float b){
    ull r; asm("mov.b64 %0, {%1, %2};" : "=l"(r) : "f"(a), "f"(b)); return r;
}
__device__ __forceinline__ void unpk2(ull v, float& a, float& b){
    asm("mov.b64 {%0, %1}, %2;" : "=f"(a), "=f"(b) : "l"(v));
}
__device__ __forceinline__ void fma2(ull& d, ull a, ull b){
    asm("fma.rn.f32x2 %0, %1, %2, %0;" : "+l"(d) : "l"(a), "l"(b));
}

// ============================================================================
// Kernel 1: EW = E[50257x300] @ [W_f | W_b][300x512], fp32, f32x2 FMAs.
// 128x128 block tile, 256 threads, 8x8 per-thread microtile, K-chunks of 8.
// ============================================================================
__global__ void __launch_bounds__(256) gemm_ew(const float* __restrict__ E,
                                               const float* __restrict__ Wf,
                                               const float* __restrict__ Wb)
{
    __shared__ float As[8][128];
    __shared__ float Bs[8][128];

    const int tid = threadIdx.x;
    const int m0  = blockIdx.x * 128;
    const int nb  = blockIdx.y;                 // 0..3 -> 128-col slab of EW
    const float* Wsel = (nb < 2) ? Wf : Wb;
    const int ncol0 = (nb & 1) * 128;

    const int arow = tid >> 1, akq = tid & 1;   // A loader: row, k-quad
    const int bk   = tid >> 5, bn  = (tid & 31) * 4;  // B loader
    const int ty   = tid >> 4, tx  = tid & 15;  // compute grid 16x16

    ull acc[8][4];
    #pragma unroll
    for (int i = 0; i < 8; i++)
        #pragma unroll
        for (int j = 0; j < 4; j++) acc[i][j] = 0ull;

    for (int it = 0; it < 38; ++it){            // ceil(300/8)
        const int k0 = it * 8;

        float4 av = make_float4(0.f, 0.f, 0.f, 0.f);
        const int gm = m0 + arow;
        const int ka = k0 + akq * 4;
        if (gm < NTOK && ka < NIN)
            av = *(const float4*)(E + (size_t)gm * NIN + ka);
        As[akq*4+0][arow] = av.x;
        As[akq*4+1][arow] = av.y;
        As[akq*4+2][arow] = av.z;
        As[akq*4+3][arow] = av.w;

        float4 bv = make_float4(0.f, 0.f, 0.f, 0.f);
        const int gk = k0 + bk;
        if (gk < NIN)
            bv = *(const float4*)(Wsel + (size_t)gk * 256 + ncol0 + bn);
        *(float4*)&Bs[bk][bn] = bv;

        __syncthreads();

        #pragma unroll
        for (int kk = 0; kk < 8; ++kk){
            float4 a0 = *(const float4*)&As[kk][ty*8];
            float4 a1 = *(const float4*)&As[kk][ty*8+4];
            ulonglong2 b0 = *(const ulonglong2*)&Bs[kk][tx*8];
            ulonglong2 b1 = *(const ulonglong2*)&Bs[kk][tx*8+4];
            float am[8] = {a0.x, a0.y, a0.z, a0.w, a1.x, a1.y, a1.z, a1.w};
            #pragma unroll
            for (int i = 0; i < 8; i++){
                ull ap = pk2(am[i], am[i]);
                fma2(acc[i][0], ap, b0.x);
                fma2(acc[i][1], ap, b0.y);
                fma2(acc[i][2], ap, b1.x);
                fma2(acc[i][3], ap, b1.y);
            }
        }
        __syncthreads();
    }

    const int n0 = nb * 128;
    #pragma unroll
    for (int i = 0; i < 8; i++){
        const int gm = m0 + ty*8 + i;
        if (gm < NTOK){
            float4 o0, o1;
            unpk2(acc[i][0], o0.x, o0.y);
            unpk2(acc[i][1], o0.z, o0.w);
            unpk2(acc[i][2], o1.x, o1.y);
            unpk2(acc[i][3], o1.z, o1.w);
            float* p = g_EW + (size_t)gm * 512 + n0 + tx*8;
            *(float4*)p       = o0;
            *(float4*)(p + 4) = o1;
        }
    }
}

// ============================================================================
// Kernel 2: fused embedding-gather + LSTM recurrence + output scatter.
// Block = 16 batch rows x one direction (blockIdx.y). 256 threads:
//   k = tid&63 (hidden unit), rg = tid>>6 (row group of 4).
// U kept in shared as gate-packed float4; h kept as duplicated f32 pairs
// for broadcast LDS.64 reads + direct f32x2 FMAs. c stays in registers.
// ============================================================================
#define LSTM_SMEM (64*64*16 + 64*17*8 + 16*TT*4)   // 65536 + 8704 + 1152 = 75392

__global__ void __launch_bounds__(256) lstm_fused(
    const int*   __restrict__ cap,
    const float* __restrict__ h0f, const float* __restrict__ c0f,
    const float* __restrict__ h0b, const float* __restrict__ c0b,
    const float* __restrict__ Uf,  const float* __restrict__ bf,
    const float* __restrict__ Ub,  const float* __restrict__ bb,
    float* __restrict__ out)
{
    extern __shared__ char smraw[];
    float4 (*U4)[64]   = (float4(*)[64])smraw;                 // 64 KB
    ull    (*hT2)[17]  = (ull(*)[17])(smraw + 65536);          // 8.5 KB, padded
    int    (*toks)[TT] = (int(*)[TT])(smraw + 65536 + 8704);   // 1.1 KB

    const int dir = blockIdx.y;
    const float* U  = dir ? Ub  : Uf;
    const float* bv = dir ? bb  : bf;
    const float* h0 = dir ? h0b : h0f;
    const float* c0 = dir ? c0b : c0f;
    const int b0  = blockIdx.x * 16;
    const int tid = threadIdx.x;
    const int k   = tid & 63;
    const int rg  = tid >> 6;

    // U4[kk][k] = (U[kk][k], U[kk][k+64], U[kk][k+128], U[kk][k+192])  (i,f,g,o)
    for (int idx = tid; idx < 64*64; idx += 256){
        const int kk = idx >> 6, j = idx & 63;
        const float* up = U + kk*256 + j;
        U4[kk][j] = make_float4(up[0], up[64], up[128], up[192]);
    }
    for (int idx = tid; idx < 16*TT; idx += 256)
        toks[idx / TT][idx % TT] = cap[b0*TT + idx];
    for (int idx = tid; idx < 16*64; idx += 256){
        const int r = idx >> 6, kk = idx & 63;
        const float hv = h0[(size_t)(b0 + r)*64 + kk];
        hT2[kk][r] = pk2(hv, hv);
    }
    float c[4];
    #pragma unroll
    for (int i = 0; i < 4; i++)
        c[i] = c0[(size_t)(b0 + rg*4 + i)*64 + k];
    const float4 b4 = make_float4(bv[k], bv[k+64], bv[k+128], bv[k+192]);
    __syncthreads();

    const size_t sent_off = (size_t)BATCH * 128 * TT;

    for (int s = 0; s < TT; ++s){
        const int t = dir ? (TT - 1 - s) : s;

        // z init = bias + EW[token] (gathered from precomputed input transform)
        ull acc[4][2];
        #pragma unroll
        for (int i = 0; i < 4; i++){
            const int tok = toks[rg*4 + i][t];
            const float* ew = g_EW + (size_t)tok * 512 + dir * 256 + k;
            acc[i][0] = pk2(b4.x + ew[0],   b4.y + ew[64]);
            acc[i][1] = pk2(b4.z + ew[128], b4.w + ew[192]);
        }

        // z += h @ U  (f32x2: pair = (i,f) and (g,o) gates)
        #pragma unroll
        for (int kk = 0; kk < 64; ++kk){
            const ulonglong2 u = *(const ulonglong2*)&U4[kk][k];
            #pragma unroll
            for (int i = 0; i < 4; i++){
                const ull hp = hT2[kk][rg*4 + i];   // broadcast LDS.64
                fma2(acc[i][0], hp, u.x);
                fma2(acc[i][1], hp, u.y);
            }
        }
        __syncthreads();   // all reads of old h done

        #pragma unroll
        for (int i = 0; i < 4; i++){
            float zi, zf, zg, zo;
            unpk2(acc[i][0], zi, zf);
            unpk2(acc[i][1], zg, zo);
            const float ig = 1.f / (1.f + __expf(-zi));
            const float fg = 1.f / (1.f + __expf(-zf));
            const float gg = tanhf(zg);
            const float og = 1.f / (1.f + __expf(-zo));
            const float cn = fg * c[i] + ig * gg;
            c[i] = cn;
            const float h = og * tanhf(cn);

            const int r = rg*4 + i;
            // words_emb[b, dir*64+k, t]
            out[(size_t)(b0 + r) * (128*TT) + (dir*64 + k)*TT + t] = h;
            if (s == TT - 1)
                out[sent_off + (size_t)(b0 + r)*128 + dir*64 + k] = h;

            hT2[k][r] = pk2(h, h);
        }
        __syncthreads();   // new h visible before next step
    }
}

// ============================================================================
extern "C" void kernel_launch(void* const* d_in, const int* in_sizes, int n_in,
                              void* d_out, int out_size)
{
    const int*   captions = (const int*)  d_in[0];
    // d_in[1] = cap_lens (unused by reference)
    const float* h0f = (const float*)d_in[2];
    const float* c0f = (const float*)d_in[3];
    const float* h0b = (const float*)d_in[4];
    const float* c0b = (const float*)d_in[5];
    const float* E   = (const float*)d_in[6];
    const float* Wf  = (const float*)d_in[7];
    const float* Uf  = (const float*)d_in[8];
    const float* bf  = (const float*)d_in[9];
    const float* Wb  = (const float*)d_in[10];
    const float* Ub  = (const float*)d_in[11];
    const float* bb  = (const float*)d_in[12];
    float* out = (float*)d_out;

    cudaFuncSetAttribute(lstm_fused, cudaFuncAttributeMaxDynamicSharedMemorySize, LSTM_SMEM);

    dim3 gg((NTOK + 127) / 128, 4);
    gemm_ew<<<gg, 256>>>(E, Wf, Wb);

    dim3 gl(BATCH / 16, 2);
    lstm_fused<<<gl, 256, LSTM_SMEM>>>(captions, h0f, c0f, h0b, c0b,
                                       Uf, bf, Ub, bb, out);
}

// round 3
// speedup vs baseline: 1.4305x; 1.4305x over previous
#include <cuda_runtime.h>
#include <cuda_bf16.h>
#include <cstdint>

#define NTOK  50257
#define NIN   300
#define KPAD  320
#define TT    18
#define BATCH 4096

typedef unsigned long long ull;

// ---------------- device scratch (no allocations allowed) ----------------
__device__ float          g_EW [(size_t)NTOK * 512];   // plain layout: [tok][dir*256 + gate*64 + kk]
__device__ __nv_bfloat16  g_WtHi[(size_t)512 * KPAD];  // [n][k], n = dir*256 + gate*64 + kk
__device__ __nv_bfloat16  g_WtLo[(size_t)512 * KPAD];

// ---------------- f32x2 helpers (LSTM) ----------------
__device__ __forceinline__ ull pk2(float a, float b){
    ull r; asm("mov.b64 %0, {%1, %2};" : "=l"(r) : "f"(a), "f"(b)); return r;
}
__device__ __forceinline__ void unpk2(ull v, float& a, float& b){
    asm("mov.b64 {%0, %1}, %2;" : "=f"(a), "=f"(b) : "l"(v));
}
__device__ __forceinline__ void fma2(ull& d, ull a, ull b){
    asm("fma.rn.f32x2 %0, %1, %2, %0;" : "+l"(d) : "l"(a), "l"(b));
}

// ---------------- mma.sync helpers (sm_80+ baseline PTX, legal on compute_103) ----------------
__device__ __forceinline__ uint32_t smem_u32(const void* p){
    uint32_t a; asm("{ .reg .u64 t; cvta.to.shared.u64 t, %1; cvt.u32.u64 %0, t; }" : "=r"(a) : "l"(p));
    return a;
}
__device__ __forceinline__ void ldm4(uint32_t (&r)[4], uint32_t addr){
    asm volatile("ldmatrix.sync.aligned.m8n8.x4.shared.b16 {%0,%1,%2,%3}, [%4];"
        : "=r"(r[0]), "=r"(r[1]), "=r"(r[2]), "=r"(r[3]) : "r"(addr));
}
__device__ __forceinline__ void mma16816(float (&c)[4], const uint32_t (&a)[4],
                                         uint32_t b0, uint32_t b1){
    asm volatile(
        "mma.sync.aligned.m16n8k16.row.col.f32.bf16.bf16.f32 "
        "{%0,%1,%2,%3}, {%4,%5,%6,%7}, {%8,%9}, {%0,%1,%2,%3};"
        : "+f"(c[0]), "+f"(c[1]), "+f"(c[2]), "+f"(c[3])
        : "r"(a[0]), "r"(a[1]), "r"(a[2]), "r"(a[3]), "r"(b0), "r"(b1));
}
__device__ __forceinline__ uint32_t pk2bf(__nv_bfloat16 a, __nv_bfloat16 b){
    return (uint32_t)__bfloat16_as_ushort(a) | ((uint32_t)__bfloat16_as_ushort(b) << 16);
}

// ============================================================================
// prep_w: W[300x256] (f) and (b) -> bf16 hi/lo, transposed [n][KPAD], zero-pad
// ============================================================================
__global__ void prep_w(const float* __restrict__ Wf, const float* __restrict__ Wb){
    int idx = blockIdx.x * 256 + threadIdx.x;
    if (idx >= 512 * KPAD) return;
    int n = idx / KPAD, k = idx % KPAD;
    float v = 0.f;
    if (k < NIN) v = (n < 256) ? Wf[(size_t)k * 256 + n] : Wb[(size_t)k * 256 + (n - 256)];
    __nv_bfloat16 hi = __float2bfloat16_rn(v);
    __nv_bfloat16 lo = __float2bfloat16_rn(v - __bfloat162float(hi));
    g_WtHi[(size_t)n * KPAD + k] = hi;
    g_WtLo[(size_t)n * KPAD + k] = lo;
}

// ============================================================================
// gemm_tc: g_EW[m][n] = sum_k E[m][k] * W[k][n]  via mma.sync bf16, 3-term split
// CTA: M=128 x N=128 (grid.x = slab 0..3 for L2 reuse of E, grid.y = m-block).
// K tiles of 32 (10 tiles, zero-padded past 300). E converted f32->hi/lo in-kernel.
// smem per stage: Ehi|Elo|Bhi|Blo, 128 rows x 80B pitch (conflict-free ldmatrix).
// ============================================================================
#define KT          10
#define MAT_BYTES   10240         // 128 * 80
#define STAGE_BYTES 40960
#define G_SMEM      (2 * STAGE_BYTES)

__global__ void __launch_bounds__(256) gemm_tc(const float* __restrict__ E)
{
    extern __shared__ char sm[];
    const uint32_t smb = smem_u32(sm);
    const int tid = threadIdx.x, lane = tid & 31, wid = tid >> 5;
    const int slab = blockIdx.x;                 // 0..3 (n-slab of 128)
    const int m0   = blockIdx.y * 128;
    const int warp_m = (wid >> 2) * 64;
    const int warp_n = (wid & 3) * 32;

    // loader assignments
    const int erow = tid >> 1, eh = tid & 1;     // E: row, k-half (16 floats)
    const int wn   = tid >> 1, wc = (tid & 1) * 2;  // W: n-row, chunk pair
    const int gmE  = m0 + erow;
    const float* Ebase = E + (size_t)gmE * NIN;
    const __nv_bfloat16* WHb = g_WtHi + (size_t)(slab * 128 + wn) * KPAD;
    const __nv_bfloat16* WLb = g_WtLo + (size_t)(slab * 128 + wn) * KPAD;

    float4 eR[4]; uint4 wR[4];

    auto LDGT = [&](int kt){
        const int k0 = kt * 32;
        #pragma unroll
        for (int j = 0; j < 4; j++){
            const int k = k0 + eh * 16 + j * 4;
            eR[j] = (gmE < NTOK && k < NIN) ? *(const float4*)(Ebase + k)
                                            : make_float4(0.f, 0.f, 0.f, 0.f);
        }
        wR[0] = *(const uint4*)(WHb + k0 + wc * 8);
        wR[1] = *(const uint4*)(WHb + k0 + wc * 8 + 8);
        wR[2] = *(const uint4*)(WLb + k0 + wc * 8);
        wR[3] = *(const uint4*)(WLb + k0 + wc * 8 + 8);
    };
    auto STST = [&](int s){
        char* base = sm + s * STAGE_BYTES;
        #pragma unroll
        for (int j = 0; j < 4; j++){
            const float4 v = eR[j];
            const __nv_bfloat16 hx = __float2bfloat16_rn(v.x), hy = __float2bfloat16_rn(v.y);
            const __nv_bfloat16 hz = __float2bfloat16_rn(v.z), hw = __float2bfloat16_rn(v.w);
            const float lx = v.x - __bfloat162float(hx), ly = v.y - __bfloat162float(hy);
            const float lz = v.z - __bfloat162float(hz), lw = v.w - __bfloat162float(hw);
            const int koff = eh * 16 + j * 4;
            *(uint2*)(base + erow * 80 + koff * 2) =
                make_uint2(pk2bf(hx, hy), pk2bf(hz, hw));
            *(uint2*)(base + MAT_BYTES + erow * 80 + koff * 2) =
                make_uint2(pk2bf(__float2bfloat16_rn(lx), __float2bfloat16_rn(ly)),
                           pk2bf(__float2bfloat16_rn(lz), __float2bfloat16_rn(lw)));
        }
        *(uint4*)(base + 2*MAT_BYTES + wn * 80 + wc * 16)      = wR[0];
        *(uint4*)(base + 2*MAT_BYTES + wn * 80 + wc * 16 + 16) = wR[1];
        *(uint4*)(base + 3*MAT_BYTES + wn * 80 + wc * 16)      = wR[2];
        *(uint4*)(base + 3*MAT_BYTES + wn * 80 + wc * 16 + 16) = wR[3];
    };

    float acc[4][4][4];
    #pragma unroll
    for (int a = 0; a < 4; a++)
        #pragma unroll
        for (int b = 0; b < 4; b++)
            #pragma unroll
            for (int r = 0; r < 4; r++) acc[a][b][r] = 0.f;

    // ldmatrix lane addressing
    const int aR = warp_m + (lane & 15);
    const int aC = (lane >> 4) * 8;
    const int bR = warp_n + (lane & 7) + ((lane >> 4) << 3);
    const int bC = ((lane >> 3) & 1) * 8;

    LDGT(0); STST(0); __syncthreads();

    #pragma unroll 1
    for (int kt = 0; kt < KT; ++kt){
        if (kt + 1 < KT) LDGT(kt + 1);
        const uint32_t sb = smb + (kt & 1) * STAGE_BYTES;

        #pragma unroll
        for (int kb = 0; kb < 32; kb += 16){
            uint32_t ah[4][4], al[4][4];
            #pragma unroll
            for (int fm = 0; fm < 4; fm++){
                ldm4(ah[fm], sb + (aR + fm*16) * 80 + (aC + kb) * 2);
                ldm4(al[fm], sb + MAT_BYTES + (aR + fm*16) * 80 + (aC + kb) * 2);
            }
            uint32_t bh[4][2], bl[4][2];
            #pragma unroll
            for (int g = 0; g < 2; g++){
                uint32_t t[4];
                ldm4(t, sb + 2*MAT_BYTES + (bR + g*16) * 80 + (bC + kb) * 2);
                bh[2*g][0] = t[0]; bh[2*g][1] = t[1]; bh[2*g+1][0] = t[2]; bh[2*g+1][1] = t[3];
                ldm4(t, sb + 3*MAT_BYTES + (bR + g*16) * 80 + (bC + kb) * 2);
                bl[2*g][0] = t[0]; bl[2*g][1] = t[1]; bl[2*g+1][0] = t[2]; bl[2*g+1][1] = t[3];
            }
            #pragma unroll
            for (int fm = 0; fm < 4; fm++)
                #pragma unroll
                for (int fn = 0; fn < 4; fn++){
                    mma16816(acc[fm][fn], ah[fm], bh[fn][0], bh[fn][1]);
                    mma16816(acc[fm][fn], al[fm], bh[fn][0], bh[fn][1]);
                    mma16816(acc[fm][fn], ah[fm], bl[fn][0], bl[fn][1]);
                }
        }
        if (kt + 1 < KT) STST((kt + 1) & 1);
        __syncthreads();
    }

    // epilogue: per-thread float2 stores (sector-dense), plain layout
    const int rBase = m0 + warp_m + (lane >> 2);
    const int cBase = slab * 128 + warp_n + (lane & 3) * 2;
    #pragma unroll
    for (int fm = 0; fm < 4; fm++)
        #pragma unroll
        for (int fn = 0; fn < 4; fn++){
            const int r0 = rBase + fm * 16;
            const int cc = cBase + fn * 8;
            if (r0 < NTOK)
                *(float2*)&g_EW[(size_t)r0 * 512 + cc] =
                    make_float2(acc[fm][fn][0], acc[fm][fn][1]);
            if (r0 + 8 < NTOK)
                *(float2*)&g_EW[(size_t)(r0 + 8) * 512 + cc] =
                    make_float2(acc[fm][fn][2], acc[fm][fn][3]);
        }
}

// ============================================================================
// LSTM: block = 32 batch rows x 1 dir, 256 threads (k = tid&63, 8 rows/thread).
// U gate-packed float4 in smem; h double-buffered dup-f32x2 pairs (LDS.128
// broadcast, 1 sync/step); EW gather prefetched one step ahead.
// ============================================================================
#define LROWS 32
#define LSTM_SMEM (64*64*16 + 2*LROWS*64*8 + LROWS*TT*4)   // 100608

__global__ void __launch_bounds__(256, 2) lstm_fused(
    const int*   __restrict__ cap,
    const float* __restrict__ h0f, const float* __restrict__ c0f,
    const float* __restrict__ h0b, const float* __restrict__ c0b,
    const float* __restrict__ Uf,  const float* __restrict__ bf,
    const float* __restrict__ Ub,  const float* __restrict__ bb,
    float* __restrict__ out)
{
    extern __shared__ char smraw[];
    float4 (*U4)[64]        = (float4(*)[64])smraw;                 // 64 KB
    ull    (*h2)[LROWS][64] = (ull(*)[LROWS][64])(smraw + 65536);   // 32 KB
    int    (*toks)[TT]      = (int(*)[TT])(smraw + 65536 + 32768);  // 2.25 KB

    const int dir = blockIdx.y;
    const float* U  = dir ? Ub  : Uf;
    const float* bv = dir ? bb  : bf;
    const float* h0 = dir ? h0b : h0f;
    const float* c0 = dir ? c0b : c0f;
    const int b0  = blockIdx.x * LROWS;
    const int tid = threadIdx.x;
    const int k   = tid & 63;
    const int rg  = tid >> 6;          // 0..3, each owns 8 rows

    for (int idx = tid; idx < 64*64; idx += 256){
        const int kk = idx >> 6, j = idx & 63;
        const float* up = U + kk*256 + j;
        U4[kk][j] = make_float4(up[0], up[64], up[128], up[192]);
    }
    for (int idx = tid; idx < LROWS*TT; idx += 256)
        toks[idx / TT][idx % TT] = cap[b0*TT + idx];
    for (int idx = tid; idx < LROWS*64; idx += 256){
        const int r = idx >> 6, kk = idx & 63;
        const float hv = h0[(size_t)(b0 + r)*64 + kk];
        h2[0][r][kk] = pk2(hv, hv);
    }
    float c[8];
    #pragma unroll
    for (int i = 0; i < 8; i++)
        c[i] = c0[(size_t)(b0 + rg*8 + i)*64 + k];
    const float4 b4 = make_float4(bv[k], bv[k+64], bv[k+128], bv[k+192]);
    __syncthreads();                         // toks/U4/h2 visible

    float4 ewR[8];
    auto ldEW = [&](int s){
        const int t = dir ? (TT - 1 - s) : s;
        #pragma unroll
        for (int i = 0; i < 8; i++){
            const int tok = toks[rg*8 + i][t];
            const float* ew = g_EW + (size_t)tok*512 + dir*256 + k;
            ewR[i] = make_float4(ew[0], ew[64], ew[128], ew[192]);
        }
    };
    ldEW(0);

    const size_t sent_off = (size_t)BATCH * 128 * TT;

    for (int s = 0; s < TT; ++s){
        __syncthreads();                     // prev-step h writes visible
        const int t = dir ? (TT - 1 - s) : s;
        const int p = s & 1;

        ull acc[8][2];
        #pragma unroll
        for (int i = 0; i < 8; i++){
            acc[i][0] = pk2(b4.x + ewR[i].x, b4.y + ewR[i].y);
            acc[i][1] = pk2(b4.z + ewR[i].z, b4.w + ewR[i].w);
        }
        if (s + 1 < TT) ldEW(s + 1);         // prefetch next step's gather

        #pragma unroll 4
        for (int kk = 0; kk < 64; kk += 2){
            const ulonglong2 u0 = *(const ulonglong2*)&U4[kk][k];
            const ulonglong2 u1 = *(const ulonglong2*)&U4[kk+1][k];
            #pragma unroll
            for (int i = 0; i < 8; i++){
                const ulonglong2 hp = *(const ulonglong2*)&h2[p][rg*8 + i][kk];
                fma2(acc[i][0], hp.x, u0.x);
                fma2(acc[i][1], hp.x, u0.y);
                fma2(acc[i][0], hp.y, u1.x);
                fma2(acc[i][1], hp.y, u1.y);
            }
        }

        #pragma unroll
        for (int i = 0; i < 8; i++){
            float zi, zf, zg, zo;
            unpk2(acc[i][0], zi, zf);
            unpk2(acc[i][1], zg, zo);
            const float ig = 1.f / (1.f + __expf(-zi));
            const float fg = 1.f / (1.f + __expf(-zf));
            const float gg = tanhf(zg);
            const float og = 1.f / (1.f + __expf(-zo));
            const float cn = fg * c[i] + ig * gg;
            c[i] = cn;
            const float h = og * tanhf(cn);

            const int r = rg*8 + i;
            out[(size_t)(b0 + r) * (128*TT) + (dir*64 + k)*TT + t] = h;
            if (s == TT - 1)
                out[sent_off + (size_t)(b0 + r)*128 + dir*64 + k] = h;
            h2[p ^ 1][r][k] = pk2(h, h);
        }
    }
}

// ============================================================================
extern "C" void kernel_launch(void* const* d_in, const int* in_sizes, int n_in,
                              void* d_out, int out_size)
{
    const int*   captions = (const int*)  d_in[0];
    const float* h0f = (const float*)d_in[2];
    const float* c0f = (const float*)d_in[3];
    const float* h0b = (const float*)d_in[4];
    const float* c0b = (const float*)d_in[5];
    const float* E   = (const float*)d_in[6];
    const float* Wf  = (const float*)d_in[7];
    const float* Uf  = (const float*)d_in[8];
    const float* bf  = (const float*)d_in[9];
    const float* Wb  = (const float*)d_in[10];
    const float* Ub  = (const float*)d_in[11];
    const float* bb  = (const float*)d_in[12];
    float* out = (float*)d_out;

    cudaFuncSetAttribute(gemm_tc,    cudaFuncAttributeMaxDynamicSharedMemorySize, G_SMEM);
    cudaFuncSetAttribute(lstm_fused, cudaFuncAttributeMaxDynamicSharedMemorySize, LSTM_SMEM);

    prep_w<<<(512 * KPAD + 255) / 256, 256>>>(Wf, Wb);

    dim3 gg(4, (NTOK + 127) / 128);
    gemm_tc<<<gg, 256, G_SMEM>>>(E);

    dim3 gl(BATCH / LROWS, 2);
    lstm_fused<<<gl, 256, LSTM_SMEM>>>(captions, h0f, c0f, h0b, c0b,
                                       Uf, bf, Ub, bb, out);
}

// round 4
// speedup vs baseline: 1.4816x; 1.0357x over previous
#include <cuda_runtime.h>
#include <cuda_bf16.h>
#include <cstdint>

#define NTOK  50257
#define NIN   300
#define KPAD  320
#define TT    18
#define BATCH 4096
#define NCAP  (BATCH * TT)
#define NBLK  197              // ceil(NTOK/256)

typedef unsigned long long ull;

// ---------------- device scratch (no allocations allowed) ----------------
__device__ float          g_EW [(size_t)NTOK * 512];   // [slot][dir*256 + gate*64 + kk]
__device__ __nv_bfloat16  g_WtHi[(size_t)512 * KPAD];  // [n][k]
__device__ __nv_bfloat16  g_WtLo[(size_t)512 * KPAD];
// token dedup state (recomputed every call — deterministic)
__device__ int g_flag[NTOK];
__device__ int g_bsum[256];
__device__ int g_boff[256];
__device__ int g_list[NTOK];    // slot -> token
__device__ int g_slot[NTOK];    // token -> slot (valid for present tokens)
__device__ int g_count;

// ---------------- f32x2 helpers ----------------
__device__ __forceinline__ ull pk2(float a, float b){
    ull r; asm("mov.b64 %0, {%1, %2};" : "=l"(r) : "f"(a), "f"(b)); return r;
}
__device__ __forceinline__ void unpk2(ull v, float& a, float& b){
    asm("mov.b64 {%0, %1}, %2;" : "=f"(a), "=f"(b) : "l"(v));
}
__device__ __forceinline__ void fma2(ull& d, ull a, ull b){
    asm("fma.rn.f32x2 %0, %1, %2, %0;" : "+l"(d) : "l"(a), "l"(b));
}

// ---------------- mma.sync helpers (sm_80+ PTX, legal on compute_103) ----------------
__device__ __forceinline__ uint32_t smem_u32(const void* p){
    uint32_t a; asm("{ .reg .u64 t; cvta.to.shared.u64 t, %1; cvt.u32.u64 %0, t; }" : "=r"(a) : "l"(p));
    return a;
}
__device__ __forceinline__ void ldm4(uint32_t (&r)[4], uint32_t addr){
    asm volatile("ldmatrix.sync.aligned.m8n8.x4.shared.b16 {%0,%1,%2,%3}, [%4];"
        : "=r"(r[0]), "=r"(r[1]), "=r"(r[2]), "=r"(r[3]) : "r"(addr));
}
__device__ __forceinline__ void mma16816(float (&c)[4], const uint32_t (&a)[4],
                                         uint32_t b0, uint32_t b1){
    asm volatile(
        "mma.sync.aligned.m16n8k16.row.col.f32.bf16.bf16.f32 "
        "{%0,%1,%2,%3}, {%4,%5,%6,%7}, {%8,%9}, {%0,%1,%2,%3};"
        : "+f"(c[0]), "+f"(c[1]), "+f"(c[2]), "+f"(c[3])
        : "r"(a[0]), "r"(a[1]), "r"(a[2]), "r"(a[3]), "r"(b0), "r"(b1));
}
__device__ __forceinline__ uint32_t pk2bf(__nv_bfloat16 a, __nv_bfloat16 b){
    return (uint32_t)__bfloat16_as_ushort(a) | ((uint32_t)__bfloat16_as_ushort(b) << 16);
}

// ============================================================================
// Token dedup pipeline
// ============================================================================
__global__ void dd_zero(){
    int i = blockIdx.x * 256 + threadIdx.x;
    if (i < NTOK) g_flag[i] = 0;
}
__global__ void dd_mark(const int* __restrict__ cap){
    int i = blockIdx.x * 256 + threadIdx.x;
    if (i < NCAP) g_flag[cap[i]] = 1;
}
__global__ void dd_count(){
    __shared__ int s[256];
    int i = blockIdx.x * 256 + threadIdx.x;
    s[threadIdx.x] = (i < NTOK) ? g_flag[i] : 0;
    __syncthreads();
    for (int o = 128; o > 0; o >>= 1){
        if (threadIdx.x < o) s[threadIdx.x] += s[threadIdx.x + o];
        __syncthreads();
    }
    if (threadIdx.x == 0) g_bsum[blockIdx.x] = s[0];
}
__global__ void dd_scan(){
    __shared__ int s[256];
    const int tid = threadIdx.x;
    const int v = (tid < NBLK) ? g_bsum[tid] : 0;
    s[tid] = v; __syncthreads();
    for (int o = 1; o < 256; o <<= 1){
        int a = (tid >= o) ? s[tid - o] : 0;
        __syncthreads();
        s[tid] += a;
        __syncthreads();
    }
    g_boff[tid] = s[tid] - v;           // exclusive
    if (tid == 255) g_count = s[255];
}
__global__ void dd_emit(){
    __shared__ int s[256];
    const int tid = threadIdx.x;
    const int i = blockIdx.x * 256 + tid;
    const int v = (i < NTOK) ? g_flag[i] : 0;
    s[tid] = v; __syncthreads();
    for (int o = 1; o < 256; o <<= 1){
        int a = (tid >= o) ? s[tid - o] : 0;
        __syncthreads();
        s[tid] += a;
        __syncthreads();
    }
    if (v){
        const int pos = g_boff[blockIdx.x] + s[tid] - v;
        g_list[pos] = i;
        g_slot[i]   = pos;
    }
}

// ============================================================================
// prep_w: W -> bf16 hi/lo, transposed [n][KPAD], zero-pad
// ============================================================================
__global__ void prep_w(const float* __restrict__ Wf, const float* __restrict__ Wb){
    int idx = blockIdx.x * 256 + threadIdx.x;
    if (idx >= 512 * KPAD) return;
    int n = idx / KPAD, k = idx % KPAD;
    float v = 0.f;
    if (k < NIN) v = (n < 256) ? Wf[(size_t)k * 256 + n] : Wb[(size_t)k * 256 + (n - 256)];
    __nv_bfloat16 hi = __float2bfloat16_rn(v);
    __nv_bfloat16 lo = __float2bfloat16_rn(v - __bfloat162float(hi));
    g_WtHi[(size_t)n * KPAD + k] = hi;
    g_WtLo[(size_t)n * KPAD + k] = lo;
}

// ============================================================================
// gemm_tc: g_EW[slot][n] = sum_k E[list[slot]][k] * W[k][n], mma.sync bf16,
// 3-term hi/lo split. CTA: 128 compacted rows x 128 cols; slab-major grid.
// ============================================================================
#define KT          10
#define MAT_BYTES   10240
#define STAGE_BYTES 40960
#define G_SMEM      (2 * STAGE_BYTES)

__global__ void __launch_bounds__(256) gemm_tc(const float* __restrict__ E)
{
    const int cnt = g_count;
    const int m0  = blockIdx.y * 128;
    if (m0 >= cnt) return;

    extern __shared__ char sm[];
    const uint32_t smb = smem_u32(sm);
    const int tid = threadIdx.x, lane = tid & 31, wid = tid >> 5;
    const int slab = blockIdx.x;
    const int warp_m = (wid >> 2) * 64;
    const int warp_n = (wid & 3) * 32;

    const int erow = tid >> 1, eh = tid & 1;
    const int wn   = tid >> 1, wc = (tid & 1) * 2;
    const int gm   = m0 + erow;
    const int tokE = (gm < cnt) ? g_list[gm] : g_list[0];
    const float* Ebase = E + (size_t)tokE * NIN;
    const __nv_bfloat16* WHb = g_WtHi + (size_t)(slab * 128 + wn) * KPAD;
    const __nv_bfloat16* WLb = g_WtLo + (size_t)(slab * 128 + wn) * KPAD;

    float4 eR[4]; uint4 wR[4];

    auto LDGT = [&](int kt){
        const int k0 = kt * 32;
        #pragma unroll
        for (int j = 0; j < 4; j++){
            const int k = k0 + eh * 16 + j * 4;
            eR[j] = (k < NIN) ? *(const float4*)(Ebase + k)
                              : make_float4(0.f, 0.f, 0.f, 0.f);
        }
        wR[0] = *(const uint4*)(WHb + k0 + wc * 8);
        wR[1] = *(const uint4*)(WHb + k0 + wc * 8 + 8);
        wR[2] = *(const uint4*)(WLb + k0 + wc * 8);
        wR[3] = *(const uint4*)(WLb + k0 + wc * 8 + 8);
    };
    auto STST = [&](int s){
        char* base = sm + s * STAGE_BYTES;
        #pragma unroll
        for (int j = 0; j < 4; j++){
            const float4 v = eR[j];
            const __nv_bfloat16 hx = __float2bfloat16_rn(v.x), hy = __float2bfloat16_rn(v.y);
            const __nv_bfloat16 hz = __float2bfloat16_rn(v.z), hw = __float2bfloat16_rn(v.w);
            const float lx = v.x - __bfloat162float(hx), ly = v.y - __bfloat162float(hy);
            const float lz = v.z - __bfloat162float(hz), lw = v.w - __bfloat162float(hw);
            const int koff = eh * 16 + j * 4;
            *(uint2*)(base + erow * 80 + koff * 2) =
                make_uint2(pk2bf(hx, hy), pk2bf(hz, hw));
            *(uint2*)(base + MAT_BYTES + erow * 80 + koff * 2) =
                make_uint2(pk2bf(__float2bfloat16_rn(lx), __float2bfloat16_rn(ly)),
                           pk2bf(__float2bfloat16_rn(lz), __float2bfloat16_rn(lw)));
        }
        *(uint4*)(base + 2*MAT_BYTES + wn * 80 + wc * 16)      = wR[0];
        *(uint4*)(base + 2*MAT_BYTES + wn * 80 + wc * 16 + 16) = wR[1];
        *(uint4*)(base + 3*MAT_BYTES + wn * 80 + wc * 16)      = wR[2];
        *(uint4*)(base + 3*MAT_BYTES + wn * 80 + wc * 16 + 16) = wR[3];
    };

    float acc[4][4][4];
    #pragma unroll
    for (int a = 0; a < 4; a++)
        #pragma unroll
        for (int b = 0; b < 4; b++)
            #pragma unroll
            for (int r = 0; r < 4; r++) acc[a][b][r] = 0.f;

    const int aR = warp_m + (lane & 15);
    const int aC = (lane >> 4) * 8;
    const int bR = warp_n + (lane & 7) + ((lane >> 4) << 3);
    const int bC = ((lane >> 3) & 1) * 8;

    LDGT(0); STST(0); __syncthreads();

    #pragma unroll 1
    for (int kt = 0; kt < KT; ++kt){
        if (kt + 1 < KT) LDGT(kt + 1);
        const uint32_t sb = smb + (kt & 1) * STAGE_BYTES;

        #pragma unroll
        for (int kb = 0; kb < 32; kb += 16){
            uint32_t ah[4][4], al[4][4];
            #pragma unroll
            for (int fm = 0; fm < 4; fm++){
                ldm4(ah[fm], sb + (aR + fm*16) * 80 + (aC + kb) * 2);
                ldm4(al[fm], sb + MAT_BYTES + (aR + fm*16) * 80 + (aC + kb) * 2);
            }
            uint32_t bh[4][2], bl[4][2];
            #pragma unroll
            for (int g = 0; g < 2; g++){
                uint32_t t[4];
                ldm4(t, sb + 2*MAT_BYTES + (bR + g*16) * 80 + (bC + kb) * 2);
                bh[2*g][0] = t[0]; bh[2*g][1] = t[1]; bh[2*g+1][0] = t[2]; bh[2*g+1][1] = t[3];
                ldm4(t, sb + 3*MAT_BYTES + (bR + g*16) * 80 + (bC + kb) * 2);
                bl[2*g][0] = t[0]; bl[2*g][1] = t[1]; bl[2*g+1][0] = t[2]; bl[2*g+1][1] = t[3];
            }
            #pragma unroll
            for (int fm = 0; fm < 4; fm++)
                #pragma unroll
                for (int fn = 0; fn < 4; fn++){
                    mma16816(acc[fm][fn], ah[fm], bh[fn][0], bh[fn][1]);
                    mma16816(acc[fm][fn], al[fm], bh[fn][0], bh[fn][1]);
                    mma16816(acc[fm][fn], ah[fm], bl[fn][0], bl[fn][1]);
                }
        }
        if (kt + 1 < KT) STST((kt + 1) & 1);
        __syncthreads();
    }

    const int rBase = m0 + warp_m + (lane >> 2);
    const int cBase = slab * 128 + warp_n + (lane & 3) * 2;
    #pragma unroll
    for (int fm = 0; fm < 4; fm++)
        #pragma unroll
        for (int fn = 0; fn < 4; fn++){
            const int r0 = rBase + fm * 16;
            const int cc = cBase + fn * 8;
            if (r0 < cnt)
                *(float2*)&g_EW[(size_t)r0 * 512 + cc] =
                    make_float2(acc[fm][fn][0], acc[fm][fn][1]);
            if (r0 + 8 < cnt)
                *(float2*)&g_EW[(size_t)(r0 + 8) * 512 + cc] =
                    make_float2(acc[fm][fn][2], acc[fm][fn][3]);
        }
}

// ============================================================================
// LSTM v3: block = 64 batch rows x 1 dir (grid 128 = single wave), 256 threads,
// k = tid&63, 16 rows/thread. 1 sync/step; paired float2 words_emb stores.
// ============================================================================
#define LROWS 64
#define LSTM_SMEM (64*64*16 + 2*LROWS*64*8 + LROWS*TT*4)   // 65536+65536+4608 = 135680

__global__ void __launch_bounds__(256, 1) lstm_fused(
    const int*   __restrict__ cap,
    const float* __restrict__ h0f, const float* __restrict__ c0f,
    const float* __restrict__ h0b, const float* __restrict__ c0b,
    const float* __restrict__ Uf,  const float* __restrict__ bf,
    const float* __restrict__ Ub,  const float* __restrict__ bb,
    float* __restrict__ out)
{
    extern __shared__ char smraw[];
    float4 (*U4)[64]        = (float4(*)[64])smraw;                 // 64 KB
    ull    (*h2)[LROWS][64] = (ull(*)[LROWS][64])(smraw + 65536);   // 64 KB
    int    (*toks)[TT]      = (int(*)[TT])(smraw + 65536 + 65536);  // 4.5 KB

    const int dir = blockIdx.y;
    const float* U  = dir ? Ub  : Uf;
    const float* bv = dir ? bb  : bf;
    const float* h0 = dir ? h0b : h0f;
    const float* c0 = dir ? c0b : c0f;
    const int b0  = blockIdx.x * LROWS;
    const int tid = threadIdx.x;
    const int k   = tid & 63;
    const int rg  = tid >> 6;          // 0..3, each owns 16 rows

    for (int idx = tid; idx < 64*64; idx += 256){
        const int kk = idx >> 6, j = idx & 63;
        const float* up = U + kk*256 + j;
        U4[kk][j] = make_float4(up[0], up[64], up[128], up[192]);
    }
    for (int idx = tid; idx < LROWS*TT; idx += 256)
        toks[idx / TT][idx % TT] = g_slot[cap[b0*TT + idx]];
    for (int idx = tid; idx < LROWS*64; idx += 256){
        const int r = idx >> 6, kk = idx & 63;
        const float hv = h0[(size_t)(b0 + r)*64 + kk];
        h2[0][r][kk] = pk2(hv, hv);
    }
    float c[16];
    #pragma unroll
    for (int i = 0; i < 16; i++)
        c[i] = c0[(size_t)(b0 + rg*16 + i)*64 + k];
    const float4 b4 = make_float4(bv[k], bv[k+64], bv[k+128], bv[k+192]);

    const size_t sent_off = (size_t)BATCH * 128 * TT;
    float hprev[16];

    for (int s = 0; s < TT; ++s){
        __syncthreads();                     // prev-step h writes / init visible
        const int t = dir ? (TT - 1 - s) : s;
        const int p = s & 1;

        ull acc[16][2];
        #pragma unroll
        for (int i = 0; i < 16; i++){
            const int slot = toks[rg*16 + i][t];
            const float* ew = g_EW + (size_t)slot*512 + dir*256 + k;
            acc[i][0] = pk2(b4.x + ew[0],   b4.y + ew[64]);
            acc[i][1] = pk2(b4.z + ew[128], b4.w + ew[192]);
        }

        #pragma unroll 2
        for (int kk = 0; kk < 64; kk += 2){
            const ulonglong2 u0 = *(const ulonglong2*)&U4[kk][k];
            const ulonglong2 u1 = *(const ulonglong2*)&U4[kk+1][k];
            #pragma unroll
            for (int i = 0; i < 16; i++){
                const ulonglong2 hp = *(const ulonglong2*)&h2[p][rg*16 + i][kk];
                fma2(acc[i][0], hp.x, u0.x);
                fma2(acc[i][1], hp.x, u0.y);
                fma2(acc[i][0], hp.y, u1.x);
                fma2(acc[i][1], hp.y, u1.y);
            }
        }

        #pragma unroll
        for (int i = 0; i < 16; i++){
            float zi, zf, zg, zo;
            unpk2(acc[i][0], zi, zf);
            unpk2(acc[i][1], zg, zo);
            const float ig = 1.f / (1.f + __expf(-zi));
            const float fg = 1.f / (1.f + __expf(-zf));
            const float gg = tanhf(zg);
            const float og = 1.f / (1.f + __expf(-zo));
            const float cn = fg * c[i] + ig * gg;
            c[i] = cn;
            const float h = og * tanhf(cn);

            const int r = rg*16 + i;
            h2[p ^ 1][r][k] = pk2(h, h);
            if (s == TT - 1)
                out[sent_off + (size_t)(b0 + r)*128 + dir*64 + k] = h;

            if (s & 1){
                // forward: pair (t-1, t) = (hprev, h); backward: pair (t, t+1) = (h, hprev)
                const int tlo = dir ? t : t - 1;
                const float2 v = dir ? make_float2(h, hprev[i]) : make_float2(hprev[i], h);
                *(float2*)&out[(size_t)(b0 + r)*(128*TT) + (dir*64 + k)*TT + tlo] = v;
            } else {
                hprev[i] = h;
            }
        }
    }
}

// ============================================================================
extern "C" void kernel_launch(void* const* d_in, const int* in_sizes, int n_in,
                              void* d_out, int out_size)
{
    const int*   captions = (const int*)  d_in[0];
    const float* h0f = (const float*)d_in[2];
    const float* c0f = (const float*)d_in[3];
    const float* h0b = (const float*)d_in[4];
    const float* c0b = (const float*)d_in[5];
    const float* E   = (const float*)d_in[6];
    const float* Wf  = (const float*)d_in[7];
    const float* Uf  = (const float*)d_in[8];
    const float* bf  = (const float*)d_in[9];
    const float* Wb  = (const float*)d_in[10];
    const float* Ub  = (const float*)d_in[11];
    const float* bb  = (const float*)d_in[12];
    float* out = (float*)d_out;

    cudaFuncSetAttribute(gemm_tc,    cudaFuncAttributeMaxDynamicSharedMemorySize, G_SMEM);
    cudaFuncSetAttribute(lstm_fused, cudaFuncAttributeMaxDynamicSharedMemorySize, LSTM_SMEM);

    // dedup pipeline
    dd_zero <<<NBLK, 256>>>();
    dd_mark <<<(NCAP + 255)/256, 256>>>(captions);
    dd_count<<<NBLK, 256>>>();
    dd_scan <<<1, 256>>>();
    dd_emit <<<NBLK, 256>>>();

    prep_w<<<(512 * KPAD + 255) / 256, 256>>>(Wf, Wb);

    dim3 gg(4, (NTOK + 127) / 128);
    gemm_tc<<<gg, 256, G_SMEM>>>(E);

    dim3 gl(BATCH / LROWS, 2);
    lstm_fused<<<gl, 256, LSTM_SMEM>>>(captions, h0f, c0f, h0b, c0b,
                                       Uf, bf, Ub, bb, out);
}

// round 5
// speedup vs baseline: 1.9946x; 1.3463x over previous
#include <cuda_runtime.h>
#include <cuda_fp16.h>
#include <cstdint>

#define NTOK  50257
#define NIN   300
#define KPAD  320
#define TT    18
#define BATCH 4096
#define NCAP  (BATCH * TT)
#define NBLK  197              // ceil(NTOK/256)

typedef unsigned long long ull;

// ---------------- device scratch (no allocations allowed) ----------------
__device__ float   g_EW [(size_t)NTOK * 512];   // [slot][dir*256 + gate*64 + kk]
__device__ __half  g_Wh [(size_t)512 * KPAD];   // [n][k], fp16
// token dedup state (recomputed every call)
__device__ int g_flag[NTOK];
__device__ int g_list[NTOK];    // slot -> token
__device__ int g_slot[NTOK];    // token -> slot
__device__ int g_count;

// ---------------- f32x2 helpers ----------------
__device__ __forceinline__ ull pk2(float a, float b){
    ull r; asm("mov.b64 %0, {%1, %2};" : "=l"(r) : "f"(a), "f"(b)); return r;
}
__device__ __forceinline__ void unpk2(ull v, float& a, float& b){
    asm("mov.b64 {%0, %1}, %2;" : "=f"(a), "=f"(b) : "l"(v));
}
__device__ __forceinline__ void fma2(ull& d, ull a, ull b){
    asm("fma.rn.f32x2 %0, %1, %2, %0;" : "+l"(d) : "l"(a), "l"(b));
}
__device__ __forceinline__ float rcpa(float x){
    float r; asm("rcp.approx.f32 %0, %1;" : "=f"(r) : "f"(x)); return r;
}
__device__ __forceinline__ float sigmf(float x){          // 1/(1+e^-x)
    return rcpa(1.f + __expf(-x));
}
__device__ __forceinline__ float tanhfast(float x){       // 1 - 2/(e^{2x}+1)
    return 1.f - 2.f * rcpa(__expf(2.f * x) + 1.f);
}

// ---------------- mma.sync helpers (sm_80+ PTX, legal on compute_103) ----------------
__device__ __forceinline__ uint32_t smem_u32(const void* p){
    uint32_t a; asm("{ .reg .u64 t; cvta.to.shared.u64 t, %1; cvt.u32.u64 %0, t; }" : "=r"(a) : "l"(p));
    return a;
}
__device__ __forceinline__ void ldm4(uint32_t (&r)[4], uint32_t addr){
    asm volatile("ldmatrix.sync.aligned.m8n8.x4.shared.b16 {%0,%1,%2,%3}, [%4];"
        : "=r"(r[0]), "=r"(r[1]), "=r"(r[2]), "=r"(r[3]) : "r"(addr));
}
__device__ __forceinline__ void mma16816(float (&c)[4], const uint32_t (&a)[4],
                                         uint32_t b0, uint32_t b1){
    asm volatile(
        "mma.sync.aligned.m16n8k16.row.col.f32.f16.f16.f32 "
        "{%0,%1,%2,%3}, {%4,%5,%6,%7}, {%8,%9}, {%0,%1,%2,%3};"
        : "+f"(c[0]), "+f"(c[1]), "+f"(c[2]), "+f"(c[3])
        : "r"(a[0]), "r"(a[1]), "r"(a[2]), "r"(a[3]), "r"(b0), "r"(b1));
}
__device__ __forceinline__ uint32_t pk2h(__half a, __half b){
    return (uint32_t)__half_as_ushort(a) | ((uint32_t)__half_as_ushort(b) << 16);
}

// ============================================================================
// Token dedup: 3 kernels. Slot order is run-varying (atomics) but EW row
// VALUES are token-determined, so final output is identical.
// ============================================================================
__global__ void dd_zero(){
    int i = blockIdx.x * 256 + threadIdx.x;
    if (i < NTOK) g_flag[i] = 0;
    if (i == 0) g_count = 0;
}
__global__ void dd_mark(const int* __restrict__ cap){
    int i = blockIdx.x * 256 + threadIdx.x;
    if (i < NCAP) g_flag[cap[i]] = 1;
}
__global__ void dd_compact(){
    int i = blockIdx.x * 256 + threadIdx.x;
    if (i < NTOK && g_flag[i]){
        int pos = atomicAdd(&g_count, 1);
        g_list[pos] = i;
        g_slot[i]   = pos;
    }
}

// ============================================================================
// prep_w: W -> fp16, transposed [n][KPAD], zero-pad
// ============================================================================
__global__ void prep_w(const float* __restrict__ Wf, const float* __restrict__ Wb){
    int idx = blockIdx.x * 256 + threadIdx.x;
    if (idx >= 512 * KPAD) return;
    int n = idx / KPAD, k = idx % KPAD;
    float v = 0.f;
    if (k < NIN) v = (n < 256) ? Wf[(size_t)k * 256 + n] : Wb[(size_t)k * 256 + (n - 256)];
    g_Wh[(size_t)n * KPAD + k] = __float2half_rn(v);
}

// ============================================================================
// gemm_tc: g_EW[slot][n] = sum_k E[list[slot]][k] * W[k][n]
// mma.sync fp16, 2-term split (A = Ehi + Elo, B single fp16).
// CTA: 128 rows x 128 cols; smem/stage: Ehi|Elo|B (30720 B), 2 stages.
// K covered as 9 tiles of 32 + 1 tile of 16 (=304 >= 300).
// ============================================================================
#define KT          10
#define MAT_BYTES   10240
#define STAGE_BYTES 30720
#define G_SMEM      (2 * STAGE_BYTES)

__global__ void __launch_bounds__(256, 2) gemm_tc(const float* __restrict__ E)
{
    const int cnt = g_count;
    const int m0  = blockIdx.y * 128;
    if (m0 >= cnt) return;

    extern __shared__ char sm[];
    const uint32_t smb = smem_u32(sm);
    const int tid = threadIdx.x, lane = tid & 31, wid = tid >> 5;
    const int slab = blockIdx.x;
    const int warp_m = (wid >> 2) * 64;
    const int warp_n = (wid & 3) * 32;

    const int erow = tid >> 1, eh = tid & 1;     // E: 2 thr/row, 16 floats each
    const int wn   = tid >> 1, wc = tid & 1;     // W: 2 thr/row, 16 halves each
    const int gm   = m0 + erow;
    const int tokE = (gm < cnt) ? g_list[gm] : g_list[0];
    const float* Ebase = E + (size_t)tokE * NIN;
    const __half* WHb  = g_Wh + (size_t)(slab * 128 + wn) * KPAD;

    float4 eR[4]; uint4 wR[2];

    auto LDGT = [&](int kt){
        const int k0 = kt * 32;
        #pragma unroll
        for (int j = 0; j < 4; j++){
            const int k = k0 + eh * 16 + j * 4;
            eR[j] = (k < NIN) ? *(const float4*)(Ebase + k)
                              : make_float4(0.f, 0.f, 0.f, 0.f);
        }
        wR[0] = *(const uint4*)(WHb + k0 + wc * 16);
        wR[1] = *(const uint4*)(WHb + k0 + wc * 16 + 8);
    };
    auto STST = [&](int s){
        char* base = sm + s * STAGE_BYTES;
        #pragma unroll
        for (int j = 0; j < 4; j++){
            const float4 v = eR[j];
            const __half hx = __float2half_rn(v.x), hy = __float2half_rn(v.y);
            const __half hz = __float2half_rn(v.z), hw = __float2half_rn(v.w);
            const float lx = v.x - __half2float(hx), ly = v.y - __half2float(hy);
            const float lz = v.z - __half2float(hz), lw = v.w - __half2float(hw);
            const int koff = eh * 16 + j * 4;
            *(uint2*)(base + erow * 80 + koff * 2) =
                make_uint2(pk2h(hx, hy), pk2h(hz, hw));
            *(uint2*)(base + MAT_BYTES + erow * 80 + koff * 2) =
                make_uint2(pk2h(__float2half_rn(lx), __float2half_rn(ly)),
                           pk2h(__float2half_rn(lz), __float2half_rn(lw)));
        }
        *(uint4*)(base + 2*MAT_BYTES + wn * 80 + wc * 32)      = wR[0];
        *(uint4*)(base + 2*MAT_BYTES + wn * 80 + wc * 32 + 16) = wR[1];
    };

    float acc[4][4][4];
    #pragma unroll
    for (int a = 0; a < 4; a++)
        #pragma unroll
        for (int b = 0; b < 4; b++)
            #pragma unroll
            for (int r = 0; r < 4; r++) acc[a][b][r] = 0.f;

    const int aR = warp_m + (lane & 15);
    const int aC = (lane >> 4) * 8;
    const int bR = warp_n + (lane & 7) + ((lane >> 4) << 3);
    const int bC = ((lane >> 3) & 1) * 8;

    LDGT(0); STST(0); __syncthreads();

    #pragma unroll 1
    for (int kt = 0; kt < KT; ++kt){
        if (kt + 1 < KT) LDGT(kt + 1);
        const uint32_t sb = smb + (kt & 1) * STAGE_BYTES;

        auto DOKB = [&](int kb){
            uint32_t ah[4][4], al[4][4];
            #pragma unroll
            for (int fm = 0; fm < 4; fm++){
                ldm4(ah[fm], sb + (aR + fm*16) * 80 + (aC + kb) * 2);
                ldm4(al[fm], sb + MAT_BYTES + (aR + fm*16) * 80 + (aC + kb) * 2);
            }
            uint32_t bh[4][2];
            #pragma unroll
            for (int g = 0; g < 2; g++){
                uint32_t t[4];
                ldm4(t, sb + 2*MAT_BYTES + (bR + g*16) * 80 + (bC + kb) * 2);
                bh[2*g][0] = t[0]; bh[2*g][1] = t[1]; bh[2*g+1][0] = t[2]; bh[2*g+1][1] = t[3];
            }
            #pragma unroll
            for (int fm = 0; fm < 4; fm++)
                #pragma unroll
                for (int fn = 0; fn < 4; fn++){
                    mma16816(acc[fm][fn], ah[fm], bh[fn][0], bh[fn][1]);
                    mma16816(acc[fm][fn], al[fm], bh[fn][0], bh[fn][1]);
                }
        };
        DOKB(0);
        if (kt < KT - 1) DOKB(16);          // last tile: k 288..303 only

        if (kt + 1 < KT) STST((kt + 1) & 1);
        __syncthreads();
    }

    const int rBase = m0 + warp_m + (lane >> 2);
    const int cBase = slab * 128 + warp_n + (lane & 3) * 2;
    #pragma unroll
    for (int fm = 0; fm < 4; fm++)
        #pragma unroll
        for (int fn = 0; fn < 4; fn++){
            const int r0 = rBase + fm * 16;
            const int cc = cBase + fn * 8;
            if (r0 < cnt)
                *(float2*)&g_EW[(size_t)r0 * 512 + cc] =
                    make_float2(acc[fm][fn][0], acc[fm][fn][1]);
            if (r0 + 8 < cnt)
                *(float2*)&g_EW[(size_t)(r0 + 8) * 512 + cc] =
                    make_float2(acc[fm][fn][2], acc[fm][fn][3]);
        }
}

// ============================================================================
// LSTM v4: block = 64 batch rows x 1 dir, 512 threads (k = tid&63, 8 rows/thr,
// 4 warps/SMSP). Fast MUFU activations; 1 sync/step; paired float2 stores.
// ============================================================================
#define LROWS 64
#define LSTM_SMEM (64*64*16 + 2*LROWS*64*8 + LROWS*TT*4)   // 135680

__global__ void __launch_bounds__(512, 1) lstm_fused(
    const int*   __restrict__ cap,
    const float* __restrict__ h0f, const float* __restrict__ c0f,
    const float* __restrict__ h0b, const float* __restrict__ c0b,
    const float* __restrict__ Uf,  const float* __restrict__ bf,
    const float* __restrict__ Ub,  const float* __restrict__ bb,
    float* __restrict__ out)
{
    extern __shared__ char smraw[];
    float4 (*U4)[64]        = (float4(*)[64])smraw;                 // 64 KB
    ull    (*h2)[LROWS][64] = (ull(*)[LROWS][64])(smraw + 65536);   // 64 KB
    int    (*toks)[TT]      = (int(*)[TT])(smraw + 65536 + 65536);  // 4.5 KB

    const int dir = blockIdx.y;
    const float* U  = dir ? Ub  : Uf;
    const float* bv = dir ? bb  : bf;
    const float* h0 = dir ? h0b : h0f;
    const float* c0 = dir ? c0b : c0f;
    const int b0  = blockIdx.x * LROWS;
    const int tid = threadIdx.x;
    const int k   = tid & 63;
    const int rg  = tid >> 6;          // 0..7, each owns 8 rows

    for (int idx = tid; idx < 64*64; idx += 512){
        const int kk = idx >> 6, j = idx & 63;
        const float* up = U + kk*256 + j;
        U4[kk][j] = make_float4(up[0], up[64], up[128], up[192]);
    }
    for (int idx = tid; idx < LROWS*TT; idx += 512)
        toks[idx / TT][idx % TT] = g_slot[cap[b0*TT + idx]];
    for (int idx = tid; idx < LROWS*64; idx += 512){
        const int r = idx >> 6, kk = idx & 63;
        const float hv = h0[(size_t)(b0 + r)*64 + kk];
        h2[0][r][kk] = pk2(hv, hv);
    }
    float c[8];
    #pragma unroll
    for (int i = 0; i < 8; i++)
        c[i] = c0[(size_t)(b0 + rg*8 + i)*64 + k];
    const float4 b4 = make_float4(bv[k], bv[k+64], bv[k+128], bv[k+192]);

    const size_t sent_off = (size_t)BATCH * 128 * TT;
    float hprev[8];

    for (int s = 0; s < TT; ++s){
        __syncthreads();                     // prev-step h writes / init visible
        const int t = dir ? (TT - 1 - s) : s;
        const int p = s & 1;

        ull acc[8][2];
        #pragma unroll
        for (int i = 0; i < 8; i++){
            const int slot = toks[rg*8 + i][t];
            const float* ew = g_EW + (size_t)slot*512 + dir*256 + k;
            acc[i][0] = pk2(b4.x + ew[0],   b4.y + ew[64]);
            acc[i][1] = pk2(b4.z + ew[128], b4.w + ew[192]);
        }

        #pragma unroll 4
        for (int kk = 0; kk < 64; kk += 2){
            const ulonglong2 u0 = *(const ulonglong2*)&U4[kk][k];
            const ulonglong2 u1 = *(const ulonglong2*)&U4[kk+1][k];
            #pragma unroll
            for (int i = 0; i < 8; i++){
                const ulonglong2 hp = *(const ulonglong2*)&h2[p][rg*8 + i][kk];
                fma2(acc[i][0], hp.x, u0.x);
                fma2(acc[i][1], hp.x, u0.y);
                fma2(acc[i][0], hp.y, u1.x);
                fma2(acc[i][1], hp.y, u1.y);
            }
        }

        #pragma unroll
        for (int i = 0; i < 8; i++){
            float zi, zf, zg, zo;
            unpk2(acc[i][0], zi, zf);
            unpk2(acc[i][1], zg, zo);
            const float ig = sigmf(zi);
            const float fg = sigmf(zf);
            const float gg = tanhfast(zg);
            const float og = sigmf(zo);
            const float cn = fg * c[i] + ig * gg;
            c[i] = cn;
            const float h = og * tanhfast(cn);

            const int r = rg*8 + i;
            h2[p ^ 1][r][k] = pk2(h, h);
            if (s == TT - 1)
                out[sent_off + (size_t)(b0 + r)*128 + dir*64 + k] = h;

            if (s & 1){
                const int tlo = dir ? t : t - 1;
                const float2 v = dir ? make_float2(h, hprev[i]) : make_float2(hprev[i], h);
                *(float2*)&out[(size_t)(b0 + r)*(128*TT) + (dir*64 + k)*TT + tlo] = v;
            } else {
                hprev[i] = h;
            }
        }
    }
}

// ============================================================================
extern "C" void kernel_launch(void* const* d_in, const int* in_sizes, int n_in,
                              void* d_out, int out_size)
{
    const int*   captions = (const int*)  d_in[0];
    const float* h0f = (const float*)d_in[2];
    const float* c0f = (const float*)d_in[3];
    const float* h0b = (const float*)d_in[4];
    const float* c0b = (const float*)d_in[5];
    const float* E   = (const float*)d_in[6];
    const float* Wf  = (const float*)d_in[7];
    const float* Uf  = (const float*)d_in[8];
    const float* bf  = (const float*)d_in[9];
    const float* Wb  = (const float*)d_in[10];
    const float* Ub  = (const float*)d_in[11];
    const float* bb  = (const float*)d_in[12];
    float* out = (float*)d_out;

    cudaFuncSetAttribute(gemm_tc,    cudaFuncAttributeMaxDynamicSharedMemorySize, G_SMEM);
    cudaFuncSetAttribute(lstm_fused, cudaFuncAttributeMaxDynamicSharedMemorySize, LSTM_SMEM);

    dd_zero   <<<NBLK, 256>>>();
    dd_mark   <<<(NCAP + 255)/256, 256>>>(captions);
    dd_compact<<<NBLK, 256>>>();

    prep_w<<<(512 * KPAD + 255) / 256, 256>>>(Wf, Wb);

    dim3 gg(4, (NTOK + 127) / 128);
    gemm_tc<<<gg, 256, G_SMEM>>>(E);

    dim3 gl(BATCH / LROWS, 2);
    lstm_fused<<<gl, 512, LSTM_SMEM>>>(captions, h0f, c0f, h0b, c0b,
                                       Uf, bf, Ub, bb, out);
}

// round 6
// speedup vs baseline: 2.0050x; 1.0052x over previous
#include <cuda_runtime.h>
#include <cuda_fp16.h>
#include <cstdint>

#define NTOK  50257
#define NIN   300
#define KPAD  320
#define TT    18
#define BATCH 4096
#define NCAP  (BATCH * TT)
#define NBLK  197              // ceil(NTOK/256)

typedef unsigned long long ull;

// ---------------- device scratch (no allocations allowed) ----------------
__device__ float   g_EW [(size_t)NTOK * 512];   // [slot][dir*256 + gate*64 + kk]
__device__ __half  g_Wh [(size_t)512 * KPAD];   // [n][k], fp16
// token dedup state (recomputed every call; slot order run-varying but
// EW row VALUES are token-determined -> final output identical)
__device__ int g_flag[NTOK];
__device__ int g_list[NTOK];    // slot -> token
__device__ int g_slot[NTOK];    // token -> slot
__device__ int g_count;

// ---------------- f32x2 helpers ----------------
__device__ __forceinline__ ull pk2(float a, float b){
    ull r; asm("mov.b64 %0, {%1, %2};" : "=l"(r) : "f"(a), "f"(b)); return r;
}
__device__ __forceinline__ void unpk2(ull v, float& a, float& b){
    asm("mov.b64 {%0, %1}, %2;" : "=f"(a), "=f"(b) : "l"(v));
}
__device__ __forceinline__ void fma2(ull& d, ull a, ull b){
    asm("fma.rn.f32x2 %0, %1, %2, %0;" : "+l"(d) : "l"(a), "l"(b));
}
__device__ __forceinline__ float rcpa(float x){
    float r; asm("rcp.approx.f32 %0, %1;" : "=f"(r) : "f"(x)); return r;
}
__device__ __forceinline__ float sigmf(float x){          // 1/(1+e^-x)
    return rcpa(1.f + __expf(-x));
}
__device__ __forceinline__ float tanhfast(float x){       // 1 - 2/(e^{2x}+1)
    return 1.f - 2.f * rcpa(__expf(2.f * x) + 1.f);
}

// ---------------- mma.sync helpers ----------------
__device__ __forceinline__ uint32_t smem_u32(const void* p){
    uint32_t a; asm("{ .reg .u64 t; cvta.to.shared.u64 t, %1; cvt.u32.u64 %0, t; }" : "=r"(a) : "l"(p));
    return a;
}
__device__ __forceinline__ void ldm4(uint32_t (&r)[4], uint32_t addr){
    asm volatile("ldmatrix.sync.aligned.m8n8.x4.shared.b16 {%0,%1,%2,%3}, [%4];"
        : "=r"(r[0]), "=r"(r[1]), "=r"(r[2]), "=r"(r[3]) : "r"(addr));
}
__device__ __forceinline__ void mma16816(float (&c)[4], const uint32_t (&a)[4],
                                         uint32_t b0, uint32_t b1){
    asm volatile(
        "mma.sync.aligned.m16n8k16.row.col.f32.f16.f16.f32 "
        "{%0,%1,%2,%3}, {%4,%5,%6,%7}, {%8,%9}, {%0,%1,%2,%3};"
        : "+f"(c[0]), "+f"(c[1]), "+f"(c[2]), "+f"(c[3])
        : "r"(a[0]), "r"(a[1]), "r"(a[2]), "r"(a[3]), "r"(b0), "r"(b1));
}
__device__ __forceinline__ uint32_t pk2h(__half a, __half b){
    return (uint32_t)__half_as_ushort(a) | ((uint32_t)__half_as_ushort(b) << 16);
}

// ============================================================================
// k_init: zero dedup flags + counter AND convert W -> fp16 transposed.
// (merged so GEMM lands at launch index 3, which is what ncu captures)
// ============================================================================
__global__ void k_init(const float* __restrict__ Wf, const float* __restrict__ Wb){
    const int idx = blockIdx.x * 256 + threadIdx.x;
    if (idx < NTOK) g_flag[idx] = 0;
    if (idx == 0)   g_count = 0;
    if (idx < 512 * KPAD){
        const int n = idx / KPAD, k = idx % KPAD;
        float v = 0.f;
        if (k < NIN) v = (n < 256) ? Wf[(size_t)k * 256 + n] : Wb[(size_t)k * 256 + (n - 256)];
        g_Wh[(size_t)n * KPAD + k] = __float2half_rn(v);
    }
}
__global__ void dd_mark(const int* __restrict__ cap){
    int i = blockIdx.x * 256 + threadIdx.x;
    if (i < NCAP) g_flag[cap[i]] = 1;
}
__global__ void dd_compact(){
    int i = blockIdx.x * 256 + threadIdx.x;
    if (i < NTOK && g_flag[i]){
        int pos = atomicAdd(&g_count, 1);
        g_list[pos] = i;
        g_slot[i]   = pos;
    }
}

// ============================================================================
// gemm_tc: g_EW[slot][n] = sum_k E[list[slot]][k] * W[k][n]
// mma.sync fp16, 2-term split (A = Ehi + Elo, B single fp16).
// CTA: 128 rows x 128 cols; 2-stage smem; K = 9x32 + 1x16 (=304).
// ============================================================================
#define KT          10
#define MAT_BYTES   10240
#define STAGE_BYTES 30720
#define G_SMEM      (2 * STAGE_BYTES)

__global__ void __launch_bounds__(256, 2) gemm_tc(const float* __restrict__ E)
{
    const int cnt = g_count;
    const int m0  = blockIdx.y * 128;
    if (m0 >= cnt) return;

    extern __shared__ char sm[];
    const uint32_t smb = smem_u32(sm);
    const int tid = threadIdx.x, lane = tid & 31, wid = tid >> 5;
    const int slab = blockIdx.x;
    const int warp_m = (wid >> 2) * 64;
    const int warp_n = (wid & 3) * 32;

    const int erow = tid >> 1, eh = tid & 1;
    const int wn   = tid >> 1, wc = tid & 1;
    const int gm   = m0 + erow;
    const int tokE = (gm < cnt) ? g_list[gm] : g_list[0];
    const float* Ebase = E + (size_t)tokE * NIN;
    const __half* WHb  = g_Wh + (size_t)(slab * 128 + wn) * KPAD;

    float4 eR[4]; uint4 wR[2];

    auto LDGT = [&](int kt){
        const int k0 = kt * 32;
        #pragma unroll
        for (int j = 0; j < 4; j++){
            const int k = k0 + eh * 16 + j * 4;
            eR[j] = (k < NIN) ? *(const float4*)(Ebase + k)
                              : make_float4(0.f, 0.f, 0.f, 0.f);
        }
        wR[0] = *(const uint4*)(WHb + k0 + wc * 16);
        wR[1] = *(const uint4*)(WHb + k0 + wc * 16 + 8);
    };
    auto STST = [&](int s){
        char* base = sm + s * STAGE_BYTES;
        #pragma unroll
        for (int j = 0; j < 4; j++){
            const float4 v = eR[j];
            const __half hx = __float2half_rn(v.x), hy = __float2half_rn(v.y);
            const __half hz = __float2half_rn(v.z), hw = __float2half_rn(v.w);
            const float lx = v.x - __half2float(hx), ly = v.y - __half2float(hy);
            const float lz = v.z - __half2float(hz), lw = v.w - __half2float(hw);
            const int koff = eh * 16 + j * 4;
            *(uint2*)(base + erow * 80 + koff * 2) =
                make_uint2(pk2h(hx, hy), pk2h(hz, hw));
            *(uint2*)(base + MAT_BYTES + erow * 80 + koff * 2) =
                make_uint2(pk2h(__float2half_rn(lx), __float2half_rn(ly)),
                           pk2h(__float2half_rn(lz), __float2half_rn(lw)));
        }
        *(uint4*)(base + 2*MAT_BYTES + wn * 80 + wc * 32)      = wR[0];
        *(uint4*)(base + 2*MAT_BYTES + wn * 80 + wc * 32 + 16) = wR[1];
    };

    float acc[4][4][4];
    #pragma unroll
    for (int a = 0; a < 4; a++)
        #pragma unroll
        for (int b = 0; b < 4; b++)
            #pragma unroll
            for (int r = 0; r < 4; r++) acc[a][b][r] = 0.f;

    const int aR = warp_m + (lane & 15);
    const int aC = (lane >> 4) * 8;
    const int bR = warp_n + (lane & 7) + ((lane >> 4) << 3);
    const int bC = ((lane >> 3) & 1) * 8;

    LDGT(0); STST(0); __syncthreads();

    #pragma unroll 1
    for (int kt = 0; kt < KT; ++kt){
        if (kt + 1 < KT) LDGT(kt + 1);
        const uint32_t sb = smb + (kt & 1) * STAGE_BYTES;

        auto DOKB = [&](int kb){
            uint32_t ah[4][4], al[4][4];
            #pragma unroll
            for (int fm = 0; fm < 4; fm++){
                ldm4(ah[fm], sb + (aR + fm*16) * 80 + (aC + kb) * 2);
                ldm4(al[fm], sb + MAT_BYTES + (aR + fm*16) * 80 + (aC + kb) * 2);
            }
            uint32_t bh[4][2];
            #pragma unroll
            for (int g = 0; g < 2; g++){
                uint32_t t[4];
                ldm4(t, sb + 2*MAT_BYTES + (bR + g*16) * 80 + (bC + kb) * 2);
                bh[2*g][0] = t[0]; bh[2*g][1] = t[1]; bh[2*g+1][0] = t[2]; bh[2*g+1][1] = t[3];
            }
            #pragma unroll
            for (int fm = 0; fm < 4; fm++)
                #pragma unroll
                for (int fn = 0; fn < 4; fn++){
                    mma16816(acc[fm][fn], ah[fm], bh[fn][0], bh[fn][1]);
                    mma16816(acc[fm][fn], al[fm], bh[fn][0], bh[fn][1]);
                }
        };
        DOKB(0);
        if (kt < KT - 1) DOKB(16);

        if (kt + 1 < KT) STST((kt + 1) & 1);
        __syncthreads();
    }

    const int rBase = m0 + warp_m + (lane >> 2);
    const int cBase = slab * 128 + warp_n + (lane & 3) * 2;
    #pragma unroll
    for (int fm = 0; fm < 4; fm++)
        #pragma unroll
        for (int fn = 0; fn < 4; fn++){
            const int r0 = rBase + fm * 16;
            const int cc = cBase + fn * 8;
            if (r0 < cnt)
                *(float2*)&g_EW[(size_t)r0 * 512 + cc] =
                    make_float2(acc[fm][fn][0], acc[fm][fn][1]);
            if (r0 + 8 < cnt)
                *(float2*)&g_EW[(size_t)(r0 + 8) * 512 + cc] =
                    make_float2(acc[fm][fn][2], acc[fm][fn][3]);
        }
}

// ============================================================================
// LSTM v5: block = 64 rows x 1 dir, 512 threads, 8 rows/thread.
// EW gather issued at step start, ADDED in epilogue (hides LDG latency
// behind the ~8k-cycle fma loop). 1 sync/step; paired float2 stores.
// ============================================================================
#define LROWS 64
#define LSTM_SMEM (64*64*16 + 2*LROWS*64*8 + LROWS*TT*4)   // 135680

__global__ void __launch_bounds__(512, 1) lstm_fused(
    const int*   __restrict__ cap,
    const float* __restrict__ h0f, const float* __restrict__ c0f,
    const float* __restrict__ h0b, const float* __restrict__ c0b,
    const float* __restrict__ Uf,  const float* __restrict__ bf,
    const float* __restrict__ Ub,  const float* __restrict__ bb,
    float* __restrict__ out)
{
    extern __shared__ char smraw[];
    float4 (*U4)[64]        = (float4(*)[64])smraw;                 // 64 KB
    ull    (*h2)[LROWS][64] = (ull(*)[LROWS][64])(smraw + 65536);   // 64 KB
    int    (*toks)[TT]      = (int(*)[TT])(smraw + 65536 + 65536);  // 4.5 KB

    const int dir = blockIdx.y;
    const float* U  = dir ? Ub  : Uf;
    const float* bv = dir ? bb  : bf;
    const float* h0 = dir ? h0b : h0f;
    const float* c0 = dir ? c0b : c0f;
    const int b0  = blockIdx.x * LROWS;
    const int tid = threadIdx.x;
    const int k   = tid & 63;
    const int rg  = tid >> 6;          // 0..7, each owns 8 rows

    for (int idx = tid; idx < 64*64; idx += 512){
        const int kk = idx >> 6, j = idx & 63;
        const float* up = U + kk*256 + j;
        U4[kk][j] = make_float4(up[0], up[64], up[128], up[192]);
    }
    for (int idx = tid; idx < LROWS*TT; idx += 512)
        toks[idx / TT][idx % TT] = g_slot[cap[b0*TT + idx]];
    for (int idx = tid; idx < LROWS*64; idx += 512){
        const int r = idx >> 6, kk = idx & 63;
        const float hv = h0[(size_t)(b0 + r)*64 + kk];
        h2[0][r][kk] = pk2(hv, hv);
    }
    float c[8];
    #pragma unroll
    for (int i = 0; i < 8; i++)
        c[i] = c0[(size_t)(b0 + rg*8 + i)*64 + k];
    const float4 b4 = make_float4(bv[k], bv[k+64], bv[k+128], bv[k+192]);

    const size_t sent_off = (size_t)BATCH * 128 * TT;
    float hprev[8];

    for (int s = 0; s < TT; ++s){
        __syncthreads();                     // prev-step h writes / init visible
        const int t = dir ? (TT - 1 - s) : s;
        const int p = s & 1;

        // EW gather: issue now, consume in epilogue (~8k cycles later)
        float ewv[8][4];
        #pragma unroll
        for (int i = 0; i < 8; i++){
            const int slot = toks[rg*8 + i][t];
            const float* ew = g_EW + (size_t)slot*512 + dir*256 + k;
            ewv[i][0] = ew[0];   ewv[i][1] = ew[64];
            ewv[i][2] = ew[128]; ewv[i][3] = ew[192];
        }

        ull acc[8][2];
        #pragma unroll
        for (int i = 0; i < 8; i++){
            acc[i][0] = pk2(b4.x, b4.y);
            acc[i][1] = pk2(b4.z, b4.w);
        }

        #pragma unroll 2
        for (int kk = 0; kk < 64; kk += 2){
            const ulonglong2 u0 = *(const ulonglong2*)&U4[kk][k];
            const ulonglong2 u1 = *(const ulonglong2*)&U4[kk+1][k];
            #pragma unroll
            for (int i = 0; i < 8; i++){
                const ulonglong2 hp = *(const ulonglong2*)&h2[p][rg*8 + i][kk];
                fma2(acc[i][0], hp.x, u0.x);
                fma2(acc[i][1], hp.x, u0.y);
                fma2(acc[i][0], hp.y, u1.x);
                fma2(acc[i][1], hp.y, u1.y);
            }
        }

        #pragma unroll
        for (int i = 0; i < 8; i++){
            float zi, zf, zg, zo;
            unpk2(acc[i][0], zi, zf);
            unpk2(acc[i][1], zg, zo);
            zi += ewv[i][0]; zf += ewv[i][1];
            zg += ewv[i][2]; zo += ewv[i][3];
            const float ig = sigmf(zi);
            const float fg = sigmf(zf);
            const float gg = tanhfast(zg);
            const float og = sigmf(zo);
            const float cn = fg * c[i] + ig * gg;
            c[i] = cn;
            const float h = og * tanhfast(cn);

            const int r = rg*8 + i;
            h2[p ^ 1][r][k] = pk2(h, h);
            if (s == TT - 1)
                out[sent_off + (size_t)(b0 + r)*128 + dir*64 + k] = h;

            if (s & 1){
                const int tlo = dir ? t : t - 1;
                const float2 v = dir ? make_float2(h, hprev[i]) : make_float2(hprev[i], h);
                *(float2*)&out[(size_t)(b0 + r)*(128*TT) + (dir*64 + k)*TT + tlo] = v;
            } else {
                hprev[i] = h;
            }
        }
    }
}

// ============================================================================
extern "C" void kernel_launch(void* const* d_in, const int* in_sizes, int n_in,
                              void* d_out, int out_size)
{
    const int*   captions = (const int*)  d_in[0];
    const float* h0f = (const float*)d_in[2];
    const float* c0f = (const float*)d_in[3];
    const float* h0b = (const float*)d_in[4];
    const float* c0b = (const float*)d_in[5];
    const float* E   = (const float*)d_in[6];
    const float* Wf  = (const float*)d_in[7];
    const float* Uf  = (const float*)d_in[8];
    const float* bf  = (const float*)d_in[9];
    const float* Wb  = (const float*)d_in[10];
    const float* Ub  = (const float*)d_in[11];
    const float* bb  = (const float*)d_in[12];
    float* out = (float*)d_out;

    cudaFuncSetAttribute(gemm_tc,    cudaFuncAttributeMaxDynamicSharedMemorySize, G_SMEM);
    cudaFuncSetAttribute(lstm_fused, cudaFuncAttributeMaxDynamicSharedMemorySize, LSTM_SMEM);

    // launch index:      0       1        2         3 (<- ncu capture)  4
    k_init    <<<640, 256>>>(Wf, Wb);
    dd_mark   <<<(NCAP + 255)/256, 256>>>(captions);
    dd_compact<<<NBLK, 256>>>();

    dim3 gg(4, (NTOK + 127) / 128);
    gemm_tc<<<gg, 256, G_SMEM>>>(E);

    dim3 gl(BATCH / LROWS, 2);
    lstm_fused<<<gl, 512, LSTM_SMEM>>>(captions, h0f, c0f, h0b, c0b,
                                       Uf, bf, Ub, bb, out);
}